// round 1
// baseline (speedup 1.0000x reference)
#include <cuda_runtime.h>

// Problem constants
#define BATCH  256
#define SEQ    100
#define CH     512
#define MTOT   (BATCH*SEQ)     // 25600
#define DIMIN  2048
#define LAYERS 6

// GEMM tile config
#define BM 128
#define BN 128
#define BK 8
#define SPAD 4

// ---------------------------------------------------------------------------
// Scratch (device globals: allocation inside kernel_launch is forbidden)
// ---------------------------------------------------------------------------
__device__ float g_X [MTOT*CH];
__device__ float g_G [MTOT*CH];
__device__ float g_TH[MTOT*CH];
__device__ float g_PH[MTOT*CH];
__device__ float g_R [BATCH*SEQ*SEQ];
__device__ float g_Y [MTOT*CH];

// ---------------------------------------------------------------------------
// Packed fp32x2 helpers (FFMA2 path: 2 FMAs per issued instruction)
// ---------------------------------------------------------------------------
__device__ __forceinline__ unsigned long long packf2(float lo, float hi){
    unsigned long long d;
    asm("mov.b64 %0, {%1, %2};" : "=l"(d) : "f"(lo), "f"(hi));
    return d;
}
__device__ __forceinline__ float2 unpackf2(unsigned long long v){
    float2 r;
    asm("mov.b64 {%0, %1}, %2;" : "=f"(r.x), "=f"(r.y) : "l"(v));
    return r;
}
__device__ __forceinline__ void fma2(unsigned long long &acc,
                                     unsigned long long a,
                                     unsigned long long b){
    asm("fma.rn.f32x2 %0, %1, %2, %0;" : "+l"(acc) : "l"(a), "l"(b));
}

// Shared inner-product step: 8 k-steps of the 8x8 microtile in f32x2.
// acc[i][j] holds output columns (tx*8 + 2j, tx*8 + 2j + 1) for row ty*8+i.
__device__ __forceinline__ void mm_step(
    const float (&As)[BK][BM+SPAD], const float (&Bs)[BK][BN+SPAD],
    int tx, int ty, unsigned long long (&acc)[8][4])
{
    #pragma unroll
    for (int k = 0; k < BK; k++){
        float4 a0 = *(const float4*)&As[k][ty*8];
        float4 a1 = *(const float4*)&As[k][ty*8+4];
        float4 b0 = *(const float4*)&Bs[k][tx*8];
        float4 b1 = *(const float4*)&Bs[k][tx*8+4];
        unsigned long long bp[4];
        bp[0] = packf2(b0.x, b0.y);
        bp[1] = packf2(b0.z, b0.w);
        bp[2] = packf2(b1.x, b1.y);
        bp[3] = packf2(b1.z, b1.w);
        float av[8] = {a0.x,a0.y,a0.z,a0.w,a1.x,a1.y,a1.z,a1.w};
        #pragma unroll
        for (int i = 0; i < 8; i++){
            unsigned long long ap = packf2(av[i], av[i]);
            fma2(acc[i][0], ap, bp[0]);
            fma2(acc[i][1], ap, bp[1]);
            fma2(acc[i][2], ap, bp[2]);
            fma2(acc[i][3], ap, bp[3]);
        }
    }
}

// ---------------------------------------------------------------------------
// Main TN GEMM: C[m,n] = sum_k A[m,k]*B[n,k]  (both operands K-major)
// MODE 0: + bias[n]
// MODE 1: out = resid + (acc + bias - mean) * (gamma*rsqrt(var+eps)) + beta
// Requires: M % BM == 0, N % BN == 0, K % BK == 0, lda/ldb % 4 == 0.
// ---------------------------------------------------------------------------
template<int MODE>
__global__ __launch_bounds__(256, 2)
void gemm_tn(const float* __restrict__ A, int lda,
             const float* __restrict__ B, int ldb,
             float* __restrict__ C, int ldc, int K,
             const float* __restrict__ bias,
             const float* __restrict__ resid,
             const float* __restrict__ gamma,
             const float* __restrict__ beta,
             const float* __restrict__ mean,
             const float* __restrict__ var)
{
    __shared__ float As[BK][BM+SPAD];
    __shared__ float Bs[BK][BN+SPAD];
    int tid = threadIdx.x;
    int tx = tid & 15, ty = tid >> 4;
    int m0 = blockIdx.y * BM;
    int n0 = blockIdx.x * BN;
    int lrow = tid >> 1;
    int lcol = (tid & 1) << 2;
    const float* Ap = A + (size_t)(m0 + lrow) * lda + lcol;
    const float* Bp = B + (size_t)(n0 + lrow) * ldb + lcol;

    unsigned long long acc[8][4];
    #pragma unroll
    for (int i = 0; i < 8; i++)
        #pragma unroll
        for (int j = 0; j < 4; j++) acc[i][j] = 0ull;

    for (int k0 = 0; k0 < K; k0 += BK){
        float4 a = *(const float4*)(Ap + k0);
        float4 b = *(const float4*)(Bp + k0);
        __syncthreads();
        As[lcol+0][lrow]=a.x; As[lcol+1][lrow]=a.y;
        As[lcol+2][lrow]=a.z; As[lcol+3][lrow]=a.w;
        Bs[lcol+0][lrow]=b.x; Bs[lcol+1][lrow]=b.y;
        Bs[lcol+2][lrow]=b.z; Bs[lcol+3][lrow]=b.w;
        __syncthreads();
        mm_step(As, Bs, tx, ty, acc);
    }

    int cbase = n0 + tx*8;
    float scale[8], shift[8];
    #pragma unroll
    for (int j = 0; j < 8; j++){
        int c = cbase + j;
        if (MODE == 0){
            scale[j] = 1.0f;
            shift[j] = bias[c];
        } else {
            float iv = gamma[c] * rsqrtf(var[c] + 1e-5f);
            scale[j] = iv;
            shift[j] = (bias[c] - mean[c]) * iv + beta[c];
        }
    }
    #pragma unroll
    for (int i = 0; i < 8; i++){
        int m = m0 + ty*8 + i;
        float* Co = C + (size_t)m * ldc + cbase;
        const float* Rr = (MODE == 1) ? (resid + (size_t)m * CH + cbase) : nullptr;
        #pragma unroll
        for (int j = 0; j < 4; j++){
            float2 v = unpackf2(acc[i][j]);
            float o0 = v.x * scale[2*j]   + shift[2*j];
            float o1 = v.y * scale[2*j+1] + shift[2*j+1];
            if (MODE == 1){ o0 += Rr[2*j]; o1 += Rr[2*j+1]; }
            *(float2*)(Co + 2*j) = make_float2(o0, o1);
        }
    }
}

// ---------------------------------------------------------------------------
// R[b,n,m] = (1/SEQ) * sum_i TH[b,n,i] * PH[b,m,i]   (TN, 100x100x512)
// One block per batch; 128x128 tile covers the 100x100 output.
// ---------------------------------------------------------------------------
__global__ __launch_bounds__(256, 2)
void attn_r()
{
    int b = blockIdx.x;
    const float* A  = g_TH + (size_t)b * SEQ * CH;
    const float* Bp = g_PH + (size_t)b * SEQ * CH;
    __shared__ float As[BK][BM+SPAD];
    __shared__ float Bs[BK][BN+SPAD];
    int tid = threadIdx.x;
    int tx = tid & 15, ty = tid >> 4;
    int lrow = tid >> 1;
    int lcol = (tid & 1) << 2;
    bool ok = lrow < SEQ;

    unsigned long long acc[8][4];
    #pragma unroll
    for (int i = 0; i < 8; i++)
        #pragma unroll
        for (int j = 0; j < 4; j++) acc[i][j] = 0ull;

    for (int k0 = 0; k0 < CH; k0 += BK){
        float4 a = ok ? *(const float4*)(A  + (size_t)lrow*CH + k0 + lcol)
                      : make_float4(0.f,0.f,0.f,0.f);
        float4 c = ok ? *(const float4*)(Bp + (size_t)lrow*CH + k0 + lcol)
                      : make_float4(0.f,0.f,0.f,0.f);
        __syncthreads();
        As[lcol+0][lrow]=a.x; As[lcol+1][lrow]=a.y;
        As[lcol+2][lrow]=a.z; As[lcol+3][lrow]=a.w;
        Bs[lcol+0][lrow]=c.x; Bs[lcol+1][lrow]=c.y;
        Bs[lcol+2][lrow]=c.z; Bs[lcol+3][lrow]=c.w;
        __syncthreads();
        mm_step(As, Bs, tx, ty, acc);
    }

    float* Ro = g_R + (size_t)b * SEQ * SEQ;
    const float inv_n = 1.0f / (float)SEQ;
    #pragma unroll
    for (int i = 0; i < 8; i++){
        int m = ty*8 + i;
        if (m < SEQ){
            #pragma unroll
            for (int j = 0; j < 4; j++){
                float2 v = unpackf2(acc[i][j]);
                int n = tx*8 + 2*j;
                if (n   < SEQ) Ro[m*SEQ + n]     = v.x * inv_n;
                if (n+1 < SEQ) Ro[m*SEQ + n + 1] = v.y * inv_n;
            }
        }
    }
}

// ---------------------------------------------------------------------------
// Y[b,n,i] = sum_m R[b,n,m] * G[b,m,i]   (NN, M=100, K=100, N=512)
// grid.x = CH/BN tiles, grid.y = batch
// ---------------------------------------------------------------------------
__global__ __launch_bounds__(256, 2)
void attn_y()
{
    int b  = blockIdx.y;
    int n0 = blockIdx.x * BN;
    const float* A  = g_R + (size_t)b * SEQ * SEQ;   // [100,100]
    const float* Bg = g_G + (size_t)b * SEQ * CH;    // [100,512], row = k
    __shared__ float As[BK][BM+SPAD];
    __shared__ float Bs[BK][BN+SPAD];
    int tid = threadIdx.x;
    int tx = tid & 15, ty = tid >> 4;
    int lrow = tid >> 1;            // A row (m)
    int lcol = (tid & 1) << 2;      // A k sub-offset
    int brow = tid >> 5;            // B k row (0..7)
    int bcol = (tid & 31) << 2;     // B col offset

    unsigned long long acc[8][4];
    #pragma unroll
    for (int i = 0; i < 8; i++)
        #pragma unroll
        for (int j = 0; j < 4; j++) acc[i][j] = 0ull;

    for (int k0 = 0; k0 < SEQ; k0 += BK){
        float av[4];
        #pragma unroll
        for (int j = 0; j < 4; j++){
            int kk = k0 + lcol + j;
            av[j] = (lrow < SEQ && kk < SEQ) ? A[lrow*SEQ + kk] : 0.0f;
        }
        int kb = k0 + brow;
        float4 bv = (kb < SEQ) ? *(const float4*)(Bg + (size_t)kb*CH + n0 + bcol)
                               : make_float4(0.f,0.f,0.f,0.f);
        __syncthreads();
        As[lcol+0][lrow]=av[0]; As[lcol+1][lrow]=av[1];
        As[lcol+2][lrow]=av[2]; As[lcol+3][lrow]=av[3];
        *(float4*)&Bs[brow][bcol] = bv;
        __syncthreads();
        mm_step(As, Bs, tx, ty, acc);
    }

    #pragma unroll
    for (int i = 0; i < 8; i++){
        int m = ty*8 + i;
        if (m < SEQ){
            float* Yo = g_Y + (size_t)(b*SEQ + m) * CH + n0 + tx*8;
            #pragma unroll
            for (int j = 0; j < 4; j++){
                float2 v = unpackf2(acc[i][j]);
                *(float2*)(Yo + 2*j) = make_float2(v.x, v.y);
            }
        }
    }
}

// ---------------------------------------------------------------------------
// Launch
// ---------------------------------------------------------------------------
extern "C" void kernel_launch(void* const* d_in, const int* in_sizes, int n_in,
                              void* d_out, int out_size)
{
    (void)in_sizes; (void)n_in; (void)out_size;
    const float* img      = (const float*)d_in[0];
    const float* trans_w  = (const float*)d_in[1];
    const float* trans_b  = (const float*)d_in[2];
    const float* gw       = (const float*)d_in[3];
    const float* gb       = (const float*)d_in[4];
    const float* tw       = (const float*)d_in[5];
    const float* tb       = (const float*)d_in[6];
    const float* pw       = (const float*)d_in[7];
    const float* pb       = (const float*)d_in[8];
    const float* ww       = (const float*)d_in[9];
    const float* wb       = (const float*)d_in[10];
    const float* bn_gamma = (const float*)d_in[11];
    const float* bn_beta  = (const float*)d_in[12];
    const float* bn_mean  = (const float*)d_in[13];
    const float* bn_var   = (const float*)d_in[14];
    float* out = (float*)d_out;

    float *X, *G, *TH, *PH, *Y;
    cudaGetSymbolAddress((void**)&X,  g_X);
    cudaGetSymbolAddress((void**)&G,  g_G);
    cudaGetSymbolAddress((void**)&TH, g_TH);
    cudaGetSymbolAddress((void**)&PH, g_PH);
    cudaGetSymbolAddress((void**)&Y,  g_Y);

    dim3 thr(256);
    dim3 grid_big(CH/BN, MTOT/BM);   // (4, 200)

    // Encoder: X = img @ trans_w^T + trans_b
    gemm_tn<0><<<grid_big, thr>>>(img, DIMIN, trans_w, DIMIN, X, CH, DIMIN,
                                  trans_b, nullptr, nullptr, nullptr, nullptr, nullptr);

    for (int l = 0; l < LAYERS; l++){
        const float* gwl = gw + (size_t)l*CH*CH;
        const float* twl = tw + (size_t)l*CH*CH;
        const float* pwl = pw + (size_t)l*CH*CH;
        const float* wwl = ww + (size_t)l*CH*CH;
        const float* gbl = gb + (size_t)l*CH;
        const float* tbl = tb + (size_t)l*CH;
        const float* pbl = pb + (size_t)l*CH;
        const float* wbl = wb + (size_t)l*CH;

        gemm_tn<0><<<grid_big, thr>>>(X, CH, gwl, CH, G,  CH, CH,
                                      gbl, nullptr, nullptr, nullptr, nullptr, nullptr);
        gemm_tn<0><<<grid_big, thr>>>(X, CH, twl, CH, TH, CH, CH,
                                      tbl, nullptr, nullptr, nullptr, nullptr, nullptr);
        gemm_tn<0><<<grid_big, thr>>>(X, CH, pwl, CH, PH, CH, CH,
                                      pbl, nullptr, nullptr, nullptr, nullptr, nullptr);

        attn_r<<<BATCH, thr>>>();
        attn_y<<<dim3(CH/BN, BATCH), thr>>>();

        float* o = (l == LAYERS-1) ? out : X;
        gemm_tn<1><<<grid_big, thr>>>(Y, CH, wwl, CH, o, CH, CH,
                                      wbl, X,
                                      bn_gamma + (size_t)l*CH,
                                      bn_beta  + (size_t)l*CH,
                                      bn_mean  + (size_t)l*CH,
                                      bn_var   + (size_t)l*CH);
    }
}